// round 12
// baseline (speedup 1.0000x reference)
#include <cuda_runtime.h>
#include <cuda_bf16.h>
#include <math.h>
#include <stdlib.h>

#define NODES   32768
#define DD      128
#define E_NUM   524288
#define NGRAPH  512
#define NLAYER  3

typedef unsigned short u16t;
typedef unsigned int   u32t;

// ---------------- scratch (device globals) ---------------------------------
__device__ float g_x[NODES * DD];
__device__ float g_h[NODES * 256];        // gate hidden fp32
__device__ u16t  g_aggh[NODES * 128];     // agg bf16 hi plane
__device__ u16t  g_aggl[NODES * 128];     // agg bf16 lo plane
__device__ u16t  g_hh[NODES * 256];       // h bf16 hi plane
__device__ u16t  g_hl[NODES * 256];       // h bf16 lo plane
__device__ u16t  g_wh[229376];
__device__ u16t  g_wl[229376];
__device__ int   g_cnt[NODES];
__device__ int   g_off[NODES + 1];
__device__ int   g_cur[NODES];
__device__ int   g_csr[E_NUM];
__device__ float g_gate[NODES];
__device__ float g_pool[NGRAPH * DD];

#define W1_OFF(l)  ((l) * 32768)
#define W2_OFF(l)  (98304 + (l) * 32768)
#define GW_OFF     196608

static float* p_x = nullptr;   static float* p_h = nullptr;
static float* p_pool = nullptr;
static u16t* p_aggh = nullptr; static u16t* p_aggl = nullptr;
static u16t* p_hh = nullptr;   static u16t* p_hl = nullptr;
static u16t* p_wh = nullptr;   static u16t* p_wl = nullptr;

// ---------------- helpers ---------------------------------------------------
__device__ __forceinline__ u32t pack_bf2(float a, float b) {
    __nv_bfloat16 x = __float2bfloat16(a), y = __float2bfloat16(b);
    return (u32t)__bfloat16_as_ushort(x) | ((u32t)__bfloat16_as_ushort(y) << 16);
}
__device__ __forceinline__ void split2(float a, float b, u32t& hi, u32t& lo) {
    __nv_bfloat16 ha = __float2bfloat16(a), hb = __float2bfloat16(b);
    hi = (u32t)__bfloat16_as_ushort(ha) | ((u32t)__bfloat16_as_ushort(hb) << 16);
    lo = pack_bf2(a - __bfloat162float(ha), b - __bfloat162float(hb));
}
__device__ __forceinline__ void ldsm4(u32t* r, u32t addr) {
    asm volatile("ldmatrix.sync.aligned.m8n8.x4.shared.b16 {%0,%1,%2,%3}, [%4];"
                 : "=r"(r[0]), "=r"(r[1]), "=r"(r[2]), "=r"(r[3]) : "r"(addr));
}
__device__ __forceinline__ void mma16816(float* d, const u32t* a, u32t b0, u32t b1) {
    asm volatile("mma.sync.aligned.m16n8k16.row.col.f32.bf16.bf16.f32 "
                 "{%0,%1,%2,%3}, {%4,%5,%6,%7}, {%8,%9}, {%0,%1,%2,%3};"
                 : "+f"(d[0]), "+f"(d[1]), "+f"(d[2]), "+f"(d[3])
                 : "r"(a[0]), "r"(a[1]), "r"(a[2]), "r"(a[3]), "r"(b0), "r"(b1));
}

// ---------------- CSR build ------------------------------------------------
__global__ void k_zero_cnt() {
    int i = blockIdx.x * blockDim.x + threadIdx.x;
    if (i < NODES) g_cnt[i] = 0;
}
__global__ void k_count(const int* __restrict__ dst) {
    int e = blockIdx.x * blockDim.x + threadIdx.x;
    if (e < E_NUM) atomicAdd(&g_cnt[dst[e]], 1);
}
__global__ void k_scan() {
    __shared__ int s[1024];
    int tid = threadIdx.x, base = tid * 32, local = 0;
#pragma unroll
    for (int i = 0; i < 32; i++) local += g_cnt[base + i];
    s[tid] = local;
    __syncthreads();
    for (int ofs = 1; ofs < 1024; ofs <<= 1) {
        int v = (tid >= ofs) ? s[tid - ofs] : 0;
        __syncthreads();
        s[tid] += v;
        __syncthreads();
    }
    int run = s[tid] - local;
    for (int i = 0; i < 32; i++) {
        g_off[base + i] = run; g_cur[base + i] = run; run += g_cnt[base + i];
    }
    if (tid == 1023) g_off[NODES] = run;
}
__global__ void k_fill(const int* __restrict__ dst) {
    int e = blockIdx.x * blockDim.x + threadIdx.x;
    if (e < E_NUM) { int p = atomicAdd(&g_cur[dst[e]], 1); g_csr[p] = e; }
}

// ---------------- init x ----------------------------------------------------
__global__ void k_init_x(const float* __restrict__ logits,
                         const int* __restrict__ atom_feature,
                         const float* __restrict__ atom_emb) {
    int n = blockIdx.x, d = threadIdx.x;
    int b = n >> 6, j = n & 63;
    int af = atom_feature[n];
    g_x[n * DD + d] = logits[((b << 7) + j) * DD + d] + atom_emb[af * DD + d];
}

// ---------------- weight prep -----------------------------------------------
__global__ void k_prep_w(const float* __restrict__ W1,
                         const float* __restrict__ W2,
                         const float* __restrict__ GW) {
    int idx = blockIdx.x * 256 + threadIdx.x;
    if (idx >= 229376) return;
    float val;
    if (idx < 98304) {
        int l = idx >> 15, r = idx & 32767;
        int n = r >> 7, k = r & 127;
        val = W1[l * 32768 + k * 256 + n];
    } else if (idx < 196608) {
        int t = idx - 98304;
        int l = t >> 15, q = t & 32767;
        int n = q >> 8, k = q & 255;
        val = W2[l * 32768 + k * 128 + n];
    } else {
        int q = idx - 196608;
        int n = q >> 7, k = q & 127;
        val = GW[k * 256 + n];
    }
    __nv_bfloat16 h = __float2bfloat16(val);
    g_wh[idx] = __bfloat16_as_ushort(h);
    g_wl[idx] = __bfloat16_as_ushort(__float2bfloat16(val - __bfloat162float(h)));
}

// ---------------- edge aggregation -> bf16 hi/lo planes ---------------------
__global__ __launch_bounds__(256) void k_aggregate(const int* __restrict__ src,
                                                   const int* __restrict__ attr,
                                                   const float* __restrict__ edge_emb) {
    __shared__ float4 ee4[8 * 32];
    int tid = threadIdx.x;
    int warp = tid >> 5, lane = tid & 31;
    ee4[tid] = ((const float4*)edge_emb)[tid];
    __syncthreads();
    int n = blockIdx.x * 8 + warp;
    int beg = g_off[n], end = g_off[n + 1];
    float4 acc = make_float4(0.f, 0.f, 0.f, 0.f);
    const float4* x4 = (const float4*)g_x;
    for (int c0 = beg; c0 < end; c0 += 32) {
        int cnt = min(32, end - c0);
        int e = (lane < cnt) ? g_csr[c0 + lane] : 0;
        int s = (lane < cnt) ? src[e] : 0;
        int a = (lane < cnt) ? attr[e] : 0;
        int i = 0;
        for (; i + 4 <= cnt; i += 4) {
            int s0 = __shfl_sync(~0u, s, i), s1 = __shfl_sync(~0u, s, i + 1);
            int s2 = __shfl_sync(~0u, s, i + 2), s3 = __shfl_sync(~0u, s, i + 3);
            int a0 = __shfl_sync(~0u, a, i), a1 = __shfl_sync(~0u, a, i + 1);
            int a2 = __shfl_sync(~0u, a, i + 2), a3 = __shfl_sync(~0u, a, i + 3);
            float4 x0 = x4[s0 * 32 + lane], x1 = x4[s1 * 32 + lane];
            float4 x2 = x4[s2 * 32 + lane], x3 = x4[s3 * 32 + lane];
            float4 e0 = ee4[a0 * 32 + lane], e1 = ee4[a1 * 32 + lane];
            float4 e2 = ee4[a2 * 32 + lane], e3 = ee4[a3 * 32 + lane];
            acc.x += fmaxf(x0.x + e0.x, 0.f) + fmaxf(x1.x + e1.x, 0.f)
                   + fmaxf(x2.x + e2.x, 0.f) + fmaxf(x3.x + e3.x, 0.f);
            acc.y += fmaxf(x0.y + e0.y, 0.f) + fmaxf(x1.y + e1.y, 0.f)
                   + fmaxf(x2.y + e2.y, 0.f) + fmaxf(x3.y + e3.y, 0.f);
            acc.z += fmaxf(x0.z + e0.z, 0.f) + fmaxf(x1.z + e1.z, 0.f)
                   + fmaxf(x2.z + e2.z, 0.f) + fmaxf(x3.z + e3.z, 0.f);
            acc.w += fmaxf(x0.w + e0.w, 0.f) + fmaxf(x1.w + e1.w, 0.f)
                   + fmaxf(x2.w + e2.w, 0.f) + fmaxf(x3.w + e3.w, 0.f);
        }
        for (; i < cnt; i++) {
            int si = __shfl_sync(~0u, s, i);
            int ai = __shfl_sync(~0u, a, i);
            float4 xv = x4[si * 32 + lane];
            float4 ev = ee4[ai * 32 + lane];
            acc.x += fmaxf(xv.x + ev.x, 0.f);
            acc.y += fmaxf(xv.y + ev.y, 0.f);
            acc.z += fmaxf(xv.z + ev.z, 0.f);
            acc.w += fmaxf(xv.w + ev.w, 0.f);
        }
    }
    u32t h0, l0, h1, l1;
    split2(acc.x, acc.y, h0, l0);
    split2(acc.z, acc.w, h1, l1);
    ((uint2*)g_aggh)[n * 32 + lane] = make_uint2(h0, h1);
    ((uint2*)g_aggl)[n * 32 + lane] = make_uint2(l0, l1);
}

// ---------------- MMA building blocks ---------------------------------------
#define SPAD 40
// stage A from fp32 (split on the fly)
#define STAGE_A_F32(A_, K_)                                                    \
    _Pragma("unroll")                                                          \
    for (int r = 0; r < 8; r++) {                                              \
        int row = r * 16 + (tid >> 3), c4 = tid & 7;                           \
        float4 v = *(const float4*)&(A_)[(size_t)(m0 + row) * (K_) + k0 + c4 * 4]; \
        u32t hh0, ll0, hh1, ll1;                                               \
        split2(v.x, v.y, hh0, ll0);                                            \
        split2(v.z, v.w, hh1, ll1);                                            \
        *(u32t*)&sAh[row][c4 * 4]     = hh0;                                   \
        *(u32t*)&sAh[row][c4 * 4 + 2] = hh1;                                   \
        *(u32t*)&sAl[row][c4 * 4]     = ll0;                                   \
        *(u32t*)&sAl[row][c4 * 4 + 2] = ll1;                                   \
    }
// stage A from bf16 planes (pure copy)
#define STAGE_A_PLANE(Ah_, Al_, K_)                                            \
    _Pragma("unroll")                                                          \
    for (int r = 0; r < 4; r++) {                                              \
        int row = r * 32 + (tid >> 2), q = tid & 3;                            \
        *(uint4*)&sAh[row][q * 8] = *(const uint4*)&(Ah_)[(size_t)(m0 + row) * (K_) + k0 + q * 8]; \
        *(uint4*)&sAl[row][q * 8] = *(const uint4*)&(Al_)[(size_t)(m0 + row) * (K_) + k0 + q * 8]; \
    }
#define STAGE_B(Bh_, Bl_, K_)                                                  \
    _Pragma("unroll")                                                          \
    for (int r = 0; r < 4; r++) {                                              \
        int n = r * 32 + (tid >> 2), q = tid & 3;                              \
        *(uint4*)&sBh[n][q * 8] = *(const uint4*)&(Bh_)[(size_t)(bn + n) * (K_) + k0 + q * 8]; \
        *(uint4*)&sBl[n][q * 8] = *(const uint4*)&(Bl_)[(size_t)(bn + n) * (K_) + k0 + q * 8]; \
    }
// tile compute: 3-pass split-bf16, per warp M=64 x N=64
#define TILE_COMPUTE                                                           \
    _Pragma("unroll")                                                          \
    for (int ks = 0; ks < 32; ks += 16) {                                      \
        u32t ah[4][4], al[4][4], bfr[4][4];                                    \
        int arow = mw * 64 + (lane & 15);                                      \
        int acol = ks + ((lane >> 4) << 3);                                    \
        _Pragma("unroll")                                                      \
        for (int i = 0; i < 4; i++) {                                          \
            ldsm4(ah[i], (u32t)__cvta_generic_to_shared(&sAh[arow + i * 16][acol])); \
            ldsm4(al[i], (u32t)__cvta_generic_to_shared(&sAl[arow + i * 16][acol])); \
        }                                                                      \
        int gq = lane >> 3, lr = lane & 7;                                     \
        int brow_off = lr + ((gq >> 1) << 3);                                  \
        int bcol = ks + ((gq & 1) << 3);                                       \
        _Pragma("unroll")                                                      \
        for (int j = 0; j < 4; j++)                                            \
            ldsm4(bfr[j], (u32t)__cvta_generic_to_shared(&sBh[nw * 64 + j * 16 + brow_off][bcol])); \
        _Pragma("unroll")                                                      \
        for (int i = 0; i < 4; i++)                                            \
            _Pragma("unroll")                                                  \
            for (int j = 0; j < 8; j++) {                                      \
                u32t b0 = bfr[j >> 1][(j & 1) * 2], b1 = bfr[j >> 1][(j & 1) * 2 + 1]; \
                mma16816(d[i][j], ah[i], b0, b1);                              \
                mma16816(d[i][j], al[i], b0, b1);                              \
            }                                                                  \
        _Pragma("unroll")                                                      \
        for (int j = 0; j < 4; j++)                                            \
            ldsm4(bfr[j], (u32t)__cvta_generic_to_shared(&sBl[nw * 64 + j * 16 + brow_off][bcol])); \
        _Pragma("unroll")                                                      \
        for (int i = 0; i < 4; i++)                                            \
            _Pragma("unroll")                                                  \
            for (int j = 0; j < 8; j++)                                        \
                mma16816(d[i][j], ah[i],                                       \
                         bfr[j >> 1][(j & 1) * 2], bfr[j >> 1][(j & 1) * 2 + 1]); \
    }

#define DECL_MMA_VARS                                                          \
    const int tid = threadIdx.x;                                               \
    const int w = tid >> 5, lane = tid & 31;                                   \
    const int mw = w >> 1, nw = w & 1;                                         \
    float d[4][8][4];                                                          \
    _Pragma("unroll")                                                          \
    for (int i = 0; i < 4; i++)                                                \
        _Pragma("unroll")                                                      \
        for (int j = 0; j < 8; j++)                                            \
            _Pragma("unroll")                                                  \
            for (int c = 0; c < 4; c++) d[i][j][c] = 0.f;

// ---------------- gate GEMM: fp32 A, fp32 out, no relu ----------------------
__global__ __launch_bounds__(128) void k_mma_f32(const float* __restrict__ A,
                                                 const u16t* __restrict__ Bh,
                                                 const u16t* __restrict__ Bl,
                                                 const float* __restrict__ bias,
                                                 float* __restrict__ C,
                                                 int N, int K) {
    __shared__ u16t sAh[128][SPAD], sAl[128][SPAD];
    __shared__ u16t sBh[128][SPAD], sBl[128][SPAD];
    const int m0 = blockIdx.y * 128, bn = blockIdx.x * 128;
    DECL_MMA_VARS
    for (int k0 = 0; k0 < K; k0 += 32) {
        STAGE_A_F32(A, K)
        STAGE_B(Bh, Bl, K)
        __syncthreads();
        TILE_COMPUTE
        __syncthreads();
    }
#pragma unroll
    for (int i = 0; i < 4; i++)
#pragma unroll
        for (int j = 0; j < 8; j++) {
            int row = m0 + mw * 64 + i * 16 + (lane >> 2);
            int col = bn + nw * 64 + j * 8 + (lane & 3) * 2;
            float b0 = bias[col], b1 = bias[col + 1];
            *(float2*)&C[(size_t)row * N + col] =
                make_float2(d[i][j][0] + b0, d[i][j][1] + b1);
            *(float2*)&C[(size_t)(row + 8) * N + col] =
                make_float2(d[i][j][2] + b0, d[i][j][3] + b1);
        }
}

// ---------------- GEMM1: plane A, relu, plane out ---------------------------
__global__ __launch_bounds__(128) void k_mma_plane(const u16t* __restrict__ Ah,
                                                   const u16t* __restrict__ Al,
                                                   const u16t* __restrict__ Bh,
                                                   const u16t* __restrict__ Bl,
                                                   const float* __restrict__ bias,
                                                   u16t* __restrict__ Chi,
                                                   u16t* __restrict__ Clo,
                                                   int N, int K) {
    __shared__ u16t sAh[128][SPAD], sAl[128][SPAD];
    __shared__ u16t sBh[128][SPAD], sBl[128][SPAD];
    const int m0 = blockIdx.y * 128, bn = blockIdx.x * 128;
    DECL_MMA_VARS
    for (int k0 = 0; k0 < K; k0 += 32) {
        STAGE_A_PLANE(Ah, Al, K)
        STAGE_B(Bh, Bl, K)
        __syncthreads();
        TILE_COMPUTE
        __syncthreads();
    }
#pragma unroll
    for (int i = 0; i < 4; i++)
#pragma unroll
        for (int j = 0; j < 8; j++) {
            int row = m0 + mw * 64 + i * 16 + (lane >> 2);
            int col = bn + nw * 64 + j * 8 + (lane & 3) * 2;
            float b0 = bias[col], b1 = bias[col + 1];
            float c0 = fmaxf(d[i][j][0] + b0, 0.f), c1 = fmaxf(d[i][j][1] + b1, 0.f);
            float c2 = fmaxf(d[i][j][2] + b0, 0.f), c3 = fmaxf(d[i][j][3] + b1, 0.f);
            u32t hi, lo;
            split2(c0, c1, hi, lo);
            ((u32t*)Chi)[((size_t)row * N + col) >> 1] = hi;
            ((u32t*)Clo)[((size_t)row * N + col) >> 1] = lo;
            split2(c2, c3, hi, lo);
            ((u32t*)Chi)[((size_t)(row + 8) * N + col) >> 1] = hi;
            ((u32t*)Clo)[((size_t)(row + 8) * N + col) >> 1] = lo;
        }
}

// ---------------- GEMM2: plane A, fused LN + residual into g_x --------------
__global__ __launch_bounds__(128) void k_mma_ln(const u16t* __restrict__ Ah,
                                                const u16t* __restrict__ Al,
                                                const u16t* __restrict__ Bh,
                                                const u16t* __restrict__ Bl,
                                                const float* __restrict__ bias,
                                                const float* __restrict__ lg,
                                                const float* __restrict__ lb,
                                                int K) {
    __shared__ u16t sAh[128][SPAD], sAl[128][SPAD];
    __shared__ u16t sBh[128][SPAD], sBl[128][SPAD];
    const int m0 = blockIdx.y * 128, bn = 0;
    DECL_MMA_VARS
    for (int k0 = 0; k0 < K; k0 += 32) {
        STAGE_A_PLANE(Ah, Al, K)
        STAGE_B(Bh, Bl, K)
        __syncthreads();
        TILE_COMPUTE
        __syncthreads();
    }
    // alias dead staging smem for LN stats
    float (*ps)[9]  = (float (*)[9])&sAh[0][0];
    float (*pq)[9]  = (float (*)[9])&sAl[0][0];
    float* smu      = (float*)&sBh[0][0];
    float* srs      = ((float*)&sBh[0][0]) + 128;

    float bj0[8], bj1[8];
#pragma unroll
    for (int j = 0; j < 8; j++) {
        int col = nw * 64 + j * 8 + (lane & 3) * 2;
        bj0[j] = bias[col]; bj1[j] = bias[col + 1];
    }
    int pcol = nw * 4 + (lane & 3);
#pragma unroll
    for (int i = 0; i < 4; i++) {
        float s0 = 0.f, q0 = 0.f, s1 = 0.f, q1 = 0.f;
#pragma unroll
        for (int j = 0; j < 8; j++) {
            d[i][j][0] += bj0[j]; d[i][j][1] += bj1[j];
            d[i][j][2] += bj0[j]; d[i][j][3] += bj1[j];
            s0 += d[i][j][0] + d[i][j][1];
            q0 += d[i][j][0] * d[i][j][0] + d[i][j][1] * d[i][j][1];
            s1 += d[i][j][2] + d[i][j][3];
            q1 += d[i][j][2] * d[i][j][2] + d[i][j][3] * d[i][j][3];
        }
        int r0 = mw * 64 + i * 16 + (lane >> 2);
        ps[r0][pcol] = s0; pq[r0][pcol] = q0;
        ps[r0 + 8][pcol] = s1; pq[r0 + 8][pcol] = q1;
    }
    __syncthreads();
    {
        float s = 0.f, q = 0.f;
#pragma unroll
        for (int c = 0; c < 8; c++) { s += ps[tid][c]; q += pq[tid][c]; }
        float mu = s * (1.f / 128.f);
        float var = q * (1.f / 128.f) - mu * mu;
        smu[tid] = mu;
        srs[tid] = rsqrtf(var + 1e-5f);
    }
    __syncthreads();

    float lgv0[8], lgv1[8], lbv0[8], lbv1[8];
#pragma unroll
    for (int j = 0; j < 8; j++) {
        int col = nw * 64 + j * 8 + (lane & 3) * 2;
        lgv0[j] = lg[col]; lgv1[j] = lg[col + 1];
        lbv0[j] = lb[col]; lbv1[j] = lb[col + 1];
    }
#pragma unroll
    for (int i = 0; i < 4; i++) {
        int r0 = mw * 64 + i * 16 + (lane >> 2);
        float mu0 = smu[r0], rs0 = srs[r0];
        float mu1 = smu[r0 + 8], rs1 = srs[r0 + 8];
#pragma unroll
        for (int j = 0; j < 8; j++) {
            int col = nw * 64 + j * 8 + (lane & 3) * 2;
            float* xr0 = &g_x[(size_t)(m0 + r0) * 128 + col];
            float* xr1 = &g_x[(size_t)(m0 + r0 + 8) * 128 + col];
            float2 x0 = *(float2*)xr0;
            float2 x1 = *(float2*)xr1;
            x0.x += (d[i][j][0] - mu0) * rs0 * lgv0[j] + lbv0[j];
            x0.y += (d[i][j][1] - mu0) * rs0 * lgv1[j] + lbv1[j];
            x1.x += (d[i][j][2] - mu1) * rs1 * lgv0[j] + lbv0[j];
            x1.y += (d[i][j][3] - mu1) * rs1 * lgv1[j] + lbv1[j];
            *(float2*)xr0 = x0;
            *(float2*)xr1 = x1;
        }
    }
}

// ---------------- gate (warp/node) -----------------------------------------
__global__ __launch_bounds__(256) void k_gate_warp(const float* __restrict__ lng,
                                                   const float* __restrict__ lnb,
                                                   const float* __restrict__ w2,
                                                   const float* __restrict__ b2) {
    int tid = threadIdx.x;
    int warp = tid >> 5, lane = tid & 31;
    int n = blockIdx.x * 8 + warp;
    const float4* h4 = (const float4*)(g_h + n * 256);
    float4 h0 = h4[lane * 2], h1 = h4[lane * 2 + 1];
    float s = h0.x + h0.y + h0.z + h0.w + h1.x + h1.y + h1.z + h1.w;
    float q = h0.x * h0.x + h0.y * h0.y + h0.z * h0.z + h0.w * h0.w
            + h1.x * h1.x + h1.y * h1.y + h1.z * h1.z + h1.w * h1.w;
#pragma unroll
    for (int o = 16; o > 0; o >>= 1) {
        s += __shfl_xor_sync(~0u, s, o);
        q += __shfl_xor_sync(~0u, q, o);
    }
    float mu = s * (1.f / 256.f);
    float var = q * (1.f / 256.f) - mu * mu;
    float rs = rsqrtf(var + 1e-5f);
    float4 g0 = *(const float4*)&lng[lane * 8], g1 = *(const float4*)&lng[lane * 8 + 4];
    float4 c0 = *(const float4*)&lnb[lane * 8], c1 = *(const float4*)&lnb[lane * 8 + 4];
    float4 w0 = *(const float4*)&w2[lane * 8],  w1 = *(const float4*)&w2[lane * 8 + 4];
    float t = fmaxf((h0.x - mu) * rs * g0.x + c0.x, 0.f) * w0.x
            + fmaxf((h0.y - mu) * rs * g0.y + c0.y, 0.f) * w0.y
            + fmaxf((h0.z - mu) * rs * g0.z + c0.z, 0.f) * w0.z
            + fmaxf((h0.w - mu) * rs * g0.w + c0.w, 0.f) * w0.w
            + fmaxf((h1.x - mu) * rs * g1.x + c1.x, 0.f) * w1.x
            + fmaxf((h1.y - mu) * rs * g1.y + c1.y, 0.f) * w1.y
            + fmaxf((h1.z - mu) * rs * g1.z + c1.z, 0.f) * w1.z
            + fmaxf((h1.w - mu) * rs * g1.w + c1.w, 0.f) * w1.w;
#pragma unroll
    for (int o = 16; o > 0; o >>= 1) t += __shfl_xor_sync(~0u, t, o);
    if (lane == 0) g_gate[n] = t + b2[0];
}

// ---------------- pool + head ----------------------------------------------
__global__ void k_pool() {
    __shared__ float sg[64], w[64], red[64];
    int b = blockIdx.x, tid = threadIdx.x;
    if (tid < 64) sg[tid] = g_gate[b * 64 + tid];
    __syncthreads();
    if (tid < 64) red[tid] = sg[tid];
    __syncthreads();
    for (int s = 32; s > 0; s >>= 1) {
        if (tid < s) red[tid] = fmaxf(red[tid], red[tid + s]);
        __syncthreads();
    }
    float m = red[0];
    __syncthreads();
    if (tid < 64) { w[tid] = expf(sg[tid] - m); red[tid] = w[tid]; }
    __syncthreads();
    for (int s = 32; s > 0; s >>= 1) {
        if (tid < s) red[tid] += red[tid + s];
        __syncthreads();
    }
    float den = red[0];
    __syncthreads();
    if (tid < 64) w[tid] /= den;
    __syncthreads();
    float acc = 0.f;
#pragma unroll 4
    for (int j = 0; j < 64; j++) acc += w[j] * g_x[(b * 64 + j) * DD + tid];
    g_pool[b * DD + tid] = acc;
}

__device__ __forceinline__ float geluf(float x) {
    return 0.5f * x * (1.f + erff(x * 0.70710678118654752f));
}
__device__ __forceinline__ void lnStat128(float acc, float* red, float* mu, float* rs) {
    int tid = threadIdx.x;
    red[tid] = acc;
    __syncthreads();
    for (int s = 64; s > 0; s >>= 1) {
        if (tid < s) red[tid] += red[tid + s];
        __syncthreads();
    }
    float m = red[0] * (1.f / 128.f);
    __syncthreads();
    float dd = acc - m;
    red[tid] = dd * dd;
    __syncthreads();
    for (int s = 64; s > 0; s >>= 1) {
        if (tid < s) red[tid] += red[tid + s];
        __syncthreads();
    }
    float r = rsqrtf(red[0] * (1.f / 128.f) + 1e-5f);
    __syncthreads();
    *mu = m; *rs = r;
}
__global__ void k_head(const float* __restrict__ fc1W, const float* __restrict__ fc1b,
                       const float* __restrict__ ln1g, const float* __restrict__ ln1b,
                       const float* __restrict__ fc2W, const float* __restrict__ fc2b,
                       const float* __restrict__ ln2g, const float* __restrict__ ln2b,
                       const float* __restrict__ pW1, const float* __restrict__ pb1,
                       const float* __restrict__ pW2, const float* __restrict__ pb2,
                       float* __restrict__ out) {
    __shared__ float v[128], h1[128], red[128];
    int b = blockIdx.x, tid = threadIdx.x;
    v[tid] = g_pool[b * DD + tid];
    __syncthreads();
    for (int r = 0; r < 2; r++) {
        const float* W1 = fc1W + r * 16384;
        float acc = fc1b[r * 128 + tid];
        for (int k = 0; k < 128; k++) acc += v[k] * W1[k * 128 + tid];
        float mu, rs;
        lnStat128(acc, red, &mu, &rs);
        float ln = (acc - mu) * rs * ln1g[r * 128 + tid] + ln1b[r * 128 + tid];
        h1[tid] = geluf(ln);
        __syncthreads();
        const float* W2 = fc2W + r * 16384;
        float acc2 = fc2b[r * 128 + tid];
        for (int k = 0; k < 128; k++) acc2 += h1[k] * W2[k * 128 + tid];
        lnStat128(acc2, red, &mu, &rs);
        float ln2 = (acc2 - mu) * rs * ln2g[r * 128 + tid] + ln2b[r * 128 + tid];
        __syncthreads();
        v[tid] += ln2;
        __syncthreads();
    }
    float acc = pb1[tid];
    for (int k = 0; k < 128; k++) acc += v[k] * pW1[k * 128 + tid];
    h1[tid] = geluf(acc);
    __syncthreads();
    if (tid < 12) {
        float o = pb2[tid];
        for (int k = 0; k < 128; k++) o += h1[k] * pW2[k * 12 + tid];
        out[b * 12 + tid] = o;
    }
}

// ---- warm up full launch path in static init (pre-snapshot; zeros safe) ---
namespace {
struct WarmLaunch {
    WarmLaunch() {
        setenv("CUDA_MODULE_LOADING", "EAGER", 1);
        cudaSetDevice(0);
        cudaFree(0);
        void* pv = nullptr;
        cudaGetSymbolAddress(&pv, g_x);    p_x = (float*)pv;
        cudaGetSymbolAddress(&pv, g_h);    p_h = (float*)pv;
        cudaGetSymbolAddress(&pv, g_pool); p_pool = (float*)pv;
        cudaGetSymbolAddress(&pv, g_aggh); p_aggh = (u16t*)pv;
        cudaGetSymbolAddress(&pv, g_aggl); p_aggl = (u16t*)pv;
        cudaGetSymbolAddress(&pv, g_hh);   p_hh = (u16t*)pv;
        cudaGetSymbolAddress(&pv, g_hl);   p_hl = (u16t*)pv;
        cudaGetSymbolAddress(&pv, g_wh);   p_wh = (u16t*)pv;
        cudaGetSymbolAddress(&pv, g_wl);   p_wl = (u16t*)pv;
        int* icsr = nullptr; int* icnt = nullptr;
        cudaGetSymbolAddress(&pv, g_csr);  icsr = (int*)pv;
        cudaGetSymbolAddress(&pv, g_cnt);  icnt = (int*)pv;

        k_zero_cnt<<<NODES / 256, 256>>>();
        k_scan<<<1, 1024>>>();
        k_init_x<<<NODES, DD>>>(p_h, icnt, p_x);
        k_count<<<E_NUM / 256, 256>>>(icsr);
        k_fill<<<E_NUM / 256, 256>>>(icsr);
        k_aggregate<<<NODES / 8, 256>>>(icsr, icnt, p_x);
        k_prep_w<<<896, 256>>>(p_x, p_x, p_x);
        k_mma_plane<<<dim3(2, 256), 128>>>(p_aggh, p_aggl, p_wh, p_wl, p_pool,
                                           p_hh, p_hl, 256, 128);
        k_mma_ln<<<dim3(1, 256), 128>>>(p_hh, p_hl, p_wh, p_wl, p_pool,
                                        p_x, p_x, 256);
        k_mma_f32<<<dim3(2, 256), 128>>>(p_x, p_wh, p_wl, p_pool, p_h, 256, 128);
        k_gate_warp<<<NODES / 8, 256>>>(p_x, p_x, p_x, p_x);
        k_pool<<<NGRAPH, 128>>>();
        k_head<<<NGRAPH, 128>>>(p_x, p_x, p_x, p_x, p_x, p_x, p_x, p_x,
                                p_x, p_x, p_x, p_x, p_pool);
        cudaDeviceSynchronize();
    }
};
WarmLaunch s_warmLaunch;
}

// ---------------- launch ----------------------------------------------------
extern "C" void kernel_launch(void* const* d_in, const int* in_sizes, int n_in,
                              void* d_out, int out_size) {
    const float* logits     = (const float*)d_in[0];
    const int*   atom_feat  = (const int*)d_in[2];
    const int*   edge_index = (const int*)d_in[3];
    const int*   edge_attr  = (const int*)d_in[4];
    const float* atom_emb   = (const float*)d_in[6];
    const float* edge_emb   = (const float*)d_in[7];
    const float* gnn_W1     = (const float*)d_in[8];
    const float* gnn_b1     = (const float*)d_in[9];
    const float* gnn_W2     = (const float*)d_in[10];
    const float* gnn_b2     = (const float*)d_in[11];
    const float* gnn_ln_g   = (const float*)d_in[12];
    const float* gnn_ln_b   = (const float*)d_in[13];
    const float* gate_W1    = (const float*)d_in[14];
    const float* gate_b1    = (const float*)d_in[15];
    const float* gate_ln_g  = (const float*)d_in[16];
    const float* gate_ln_b  = (const float*)d_in[17];
    const float* gate_W2    = (const float*)d_in[18];
    const float* gate_b2    = (const float*)d_in[19];
    const float* res_fc1_W  = (const float*)d_in[20];
    const float* res_fc1_b  = (const float*)d_in[21];
    const float* res_ln1_g  = (const float*)d_in[22];
    const float* res_ln1_b  = (const float*)d_in[23];
    const float* res_fc2_W  = (const float*)d_in[24];
    const float* res_fc2_b  = (const float*)d_in[25];
    const float* res_ln2_g  = (const float*)d_in[26];
    const float* res_ln2_b  = (const float*)d_in[27];
    const float* pred_W1    = (const float*)d_in[28];
    const float* pred_b1    = (const float*)d_in[29];
    const float* pred_W2    = (const float*)d_in[30];
    const float* pred_b2    = (const float*)d_in[31];
    float* out = (float*)d_out;

    const int* e_src = edge_index;
    const int* e_dst = edge_index + E_NUM;

    k_zero_cnt<<<NODES / 256, 256>>>();
    k_count<<<E_NUM / 256, 256>>>(e_dst);
    k_scan<<<1, 1024>>>();
    k_fill<<<E_NUM / 256, 256>>>(e_dst);

    k_init_x<<<NODES, DD>>>(logits, atom_feat, atom_emb);
    k_prep_w<<<896, 256>>>(gnn_W1, gnn_W2, gate_W1);

    for (int l = 0; l < NLAYER; l++) {
        k_aggregate<<<NODES / 8, 256>>>(e_src, edge_attr, edge_emb);
        // h = relu(agg @ W1 + b1) -> planes
        k_mma_plane<<<dim3(2, 256), 128>>>(p_aggh, p_aggl,
                                           p_wh + W1_OFF(l), p_wl + W1_OFF(l),
                                           gnn_b1 + l * 256, p_hh, p_hl, 256, 128);
        // x += LN(h @ W2 + b2)   (fused, planes A)
        k_mma_ln<<<dim3(1, 256), 128>>>(p_hh, p_hl,
                                        p_wh + W2_OFF(l), p_wl + W2_OFF(l),
                                        gnn_b2 + l * 128,
                                        gnn_ln_g + l * 128, gnn_ln_b + l * 128, 256);
    }

    // gate hidden = x @ gate_W1 + b1
    k_mma_f32<<<dim3(2, 256), 128>>>(p_x, p_wh + GW_OFF, p_wl + GW_OFF,
                                     gate_b1, p_h, 256, 128);
    k_gate_warp<<<NODES / 8, 256>>>(gate_ln_g, gate_ln_b, gate_W2, gate_b2);
    k_pool<<<NGRAPH, 128>>>();
    k_head<<<NGRAPH, 128>>>(res_fc1_W, res_fc1_b, res_ln1_g, res_ln1_b,
                            res_fc2_W, res_fc2_b, res_ln2_g, res_ln2_b,
                            pred_W1, pred_b1, pred_W2, pred_b2, out);
    (void)in_sizes; (void)n_in; (void)out_size;
}

// round 13
// speedup vs baseline: 1.0457x; 1.0457x over previous
#include <cuda_runtime.h>
#include <cuda_bf16.h>
#include <math.h>
#include <stdlib.h>

#define NODES   32768
#define DD      128
#define E_NUM   524288
#define NGRAPH  512
#define NLAYER  3

typedef unsigned short u16t;
typedef unsigned int   u32t;

// ---------------- scratch (device globals) ---------------------------------
__device__ float g_x[NODES * DD];
__device__ float g_agg[NODES * DD];
__device__ float g_h[NODES * 256];
__device__ u16t  g_wh[229376];
__device__ u16t  g_wl[229376];
__device__ int   g_cnt[NODES];
__device__ int   g_off[NODES + 1];
__device__ int   g_cur[NODES];
__device__ int   g_csr[E_NUM];
__device__ float g_gate[NODES];
__device__ float g_pool[NGRAPH * DD];

#define W1_OFF(l)  ((l) * 32768)
#define W2_OFF(l)  (98304 + (l) * 32768)
#define GW_OFF     196608

static float* p_x = nullptr;  static float* p_agg = nullptr;
static float* p_h = nullptr;  static float* p_pool = nullptr;
static u16t* p_wh = nullptr;  static u16t* p_wl = nullptr;

// ---------------- helpers ---------------------------------------------------
__device__ __forceinline__ u32t pack_bf2(float a, float b) {
    __nv_bfloat16 x = __float2bfloat16(a), y = __float2bfloat16(b);
    return (u32t)__bfloat16_as_ushort(x) | ((u32t)__bfloat16_as_ushort(y) << 16);
}
__device__ __forceinline__ void split2(float a, float b, u32t& hi, u32t& lo) {
    __nv_bfloat16 ha = __float2bfloat16(a), hb = __float2bfloat16(b);
    hi = (u32t)__bfloat16_as_ushort(ha) | ((u32t)__bfloat16_as_ushort(hb) << 16);
    lo = pack_bf2(a - __bfloat162float(ha), b - __bfloat162float(hb));
}
__device__ __forceinline__ void ldsm4(u32t* r, u32t addr) {
    asm volatile("ldmatrix.sync.aligned.m8n8.x4.shared.b16 {%0,%1,%2,%3}, [%4];"
                 : "=r"(r[0]), "=r"(r[1]), "=r"(r[2]), "=r"(r[3]) : "r"(addr));
}
__device__ __forceinline__ void mma16816(float* d, const u32t* a, u32t b0, u32t b1) {
    asm volatile("mma.sync.aligned.m16n8k16.row.col.f32.bf16.bf16.f32 "
                 "{%0,%1,%2,%3}, {%4,%5,%6,%7}, {%8,%9}, {%0,%1,%2,%3};"
                 : "+f"(d[0]), "+f"(d[1]), "+f"(d[2]), "+f"(d[3])
                 : "r"(a[0]), "r"(a[1]), "r"(a[2]), "r"(a[3]), "r"(b0), "r"(b1));
}
#define CP16(dst, src) \
    asm volatile("cp.async.cg.shared.global [%0], [%1], 16;" :: \
        "r"((u32t)__cvta_generic_to_shared(dst)), "l"(src))
#define CP_COMMIT() asm volatile("cp.async.commit_group;" ::: "memory")

// ---------------- CSR build ------------------------------------------------
__global__ void k_zero_cnt() {
    int i = blockIdx.x * blockDim.x + threadIdx.x;
    if (i < NODES) g_cnt[i] = 0;
}
__global__ void k_count(const int* __restrict__ dst) {
    int e = blockIdx.x * blockDim.x + threadIdx.x;
    if (e < E_NUM) atomicAdd(&g_cnt[dst[e]], 1);
}
__global__ void k_scan() {
    __shared__ int s[1024];
    int tid = threadIdx.x, base = tid * 32, local = 0;
#pragma unroll
    for (int i = 0; i < 32; i++) local += g_cnt[base + i];
    s[tid] = local;
    __syncthreads();
    for (int ofs = 1; ofs < 1024; ofs <<= 1) {
        int v = (tid >= ofs) ? s[tid - ofs] : 0;
        __syncthreads();
        s[tid] += v;
        __syncthreads();
    }
    int run = s[tid] - local;
    for (int i = 0; i < 32; i++) {
        g_off[base + i] = run; g_cur[base + i] = run; run += g_cnt[base + i];
    }
    if (tid == 1023) g_off[NODES] = run;
}
__global__ void k_fill(const int* __restrict__ dst) {
    int e = blockIdx.x * blockDim.x + threadIdx.x;
    if (e < E_NUM) { int p = atomicAdd(&g_cur[dst[e]], 1); g_csr[p] = e; }
}

// ---------------- init x ----------------------------------------------------
__global__ void k_init_x(const float* __restrict__ logits,
                         const int* __restrict__ atom_feature,
                         const float* __restrict__ atom_emb) {
    int n = blockIdx.x, d = threadIdx.x;
    int b = n >> 6, j = n & 63;
    int af = atom_feature[n];
    g_x[n * DD + d] = logits[((b << 7) + j) * DD + d] + atom_emb[af * DD + d];
}

// ---------------- weight prep -----------------------------------------------
__global__ void k_prep_w(const float* __restrict__ W1,
                         const float* __restrict__ W2,
                         const float* __restrict__ GW) {
    int idx = blockIdx.x * 256 + threadIdx.x;
    if (idx >= 229376) return;
    float val;
    if (idx < 98304) {
        int l = idx >> 15, r = idx & 32767;
        int n = r >> 7, k = r & 127;
        val = W1[l * 32768 + k * 256 + n];
    } else if (idx < 196608) {
        int t = idx - 98304;
        int l = t >> 15, q = t & 32767;
        int n = q >> 8, k = q & 255;
        val = W2[l * 32768 + k * 128 + n];
    } else {
        int q = idx - 196608;
        int n = q >> 7, k = q & 127;
        val = GW[k * 256 + n];
    }
    __nv_bfloat16 h = __float2bfloat16(val);
    g_wh[idx] = __bfloat16_as_ushort(h);
    g_wl[idx] = __bfloat16_as_ushort(__float2bfloat16(val - __bfloat162float(h)));
}

// ---------------- edge aggregation ------------------------------------------
__global__ __launch_bounds__(256) void k_aggregate(const int* __restrict__ src,
                                                   const int* __restrict__ attr,
                                                   const float* __restrict__ edge_emb) {
    __shared__ float4 ee4[8 * 32];
    int tid = threadIdx.x;
    int warp = tid >> 5, lane = tid & 31;
    ee4[tid] = ((const float4*)edge_emb)[tid];
    __syncthreads();
    int n = blockIdx.x * 8 + warp;
    int beg = g_off[n], end = g_off[n + 1];
    float4 acc = make_float4(0.f, 0.f, 0.f, 0.f);
    const float4* x4 = (const float4*)g_x;
    for (int c0 = beg; c0 < end; c0 += 32) {
        int cnt = min(32, end - c0);
        int e = (lane < cnt) ? g_csr[c0 + lane] : 0;
        int s = (lane < cnt) ? src[e] : 0;
        int a = (lane < cnt) ? attr[e] : 0;
        int i = 0;
        for (; i + 4 <= cnt; i += 4) {
            int s0 = __shfl_sync(~0u, s, i), s1 = __shfl_sync(~0u, s, i + 1);
            int s2 = __shfl_sync(~0u, s, i + 2), s3 = __shfl_sync(~0u, s, i + 3);
            int a0 = __shfl_sync(~0u, a, i), a1 = __shfl_sync(~0u, a, i + 1);
            int a2 = __shfl_sync(~0u, a, i + 2), a3 = __shfl_sync(~0u, a, i + 3);
            float4 x0 = x4[s0 * 32 + lane], x1 = x4[s1 * 32 + lane];
            float4 x2 = x4[s2 * 32 + lane], x3 = x4[s3 * 32 + lane];
            float4 e0 = ee4[a0 * 32 + lane], e1 = ee4[a1 * 32 + lane];
            float4 e2 = ee4[a2 * 32 + lane], e3 = ee4[a3 * 32 + lane];
            acc.x += fmaxf(x0.x + e0.x, 0.f) + fmaxf(x1.x + e1.x, 0.f)
                   + fmaxf(x2.x + e2.x, 0.f) + fmaxf(x3.x + e3.x, 0.f);
            acc.y += fmaxf(x0.y + e0.y, 0.f) + fmaxf(x1.y + e1.y, 0.f)
                   + fmaxf(x2.y + e2.y, 0.f) + fmaxf(x3.y + e3.y, 0.f);
            acc.z += fmaxf(x0.z + e0.z, 0.f) + fmaxf(x1.z + e1.z, 0.f)
                   + fmaxf(x2.z + e2.z, 0.f) + fmaxf(x3.z + e3.z, 0.f);
            acc.w += fmaxf(x0.w + e0.w, 0.f) + fmaxf(x1.w + e1.w, 0.f)
                   + fmaxf(x2.w + e2.w, 0.f) + fmaxf(x3.w + e3.w, 0.f);
        }
        for (; i < cnt; i++) {
            int si = __shfl_sync(~0u, s, i);
            int ai = __shfl_sync(~0u, a, i);
            float4 xv = x4[si * 32 + lane];
            float4 ev = ee4[ai * 32 + lane];
            acc.x += fmaxf(xv.x + ev.x, 0.f);
            acc.y += fmaxf(xv.y + ev.y, 0.f);
            acc.z += fmaxf(xv.z + ev.z, 0.f);
            acc.w += fmaxf(xv.w + ev.w, 0.f);
        }
    }
    ((float4*)g_agg)[n * 32 + lane] = acc;
}

// ---------------- split-bf16 MMA, B double-buffered via cp.async ------------
// Dynamic smem layout (u16): sAh[128*SPAD] sAl[128*SPAD] sBh[2*128*SPAD]
// sBl[2*128*SPAD]. 61440 bytes total.
#define SPAD 40
#define DSMEM_BYTES (6 * 128 * SPAD * 2)

#define DECL_SMEM                                                              \
    extern __shared__ u16t dsm[];                                              \
    u16t* sAh = dsm;                                                           \
    u16t* sAl = dsm + 128 * SPAD;                                              \
    u16t* sBh = dsm + 2 * 128 * SPAD;                                          \
    u16t* sBl = dsm + 4 * 128 * SPAD;

#define DECL_MMA_VARS                                                          \
    const int tid = threadIdx.x;                                               \
    const int w = tid >> 5, lane = tid & 31;                                   \
    const int mw = w >> 1, nw = w & 1;                                         \
    float d[4][8][4];                                                          \
    _Pragma("unroll")                                                          \
    for (int i = 0; i < 4; i++)                                                \
        _Pragma("unroll")                                                      \
        for (int j = 0; j < 8; j++)                                            \
            _Pragma("unroll")                                                  \
            for (int c = 0; c < 4; c++) d[i][j][c] = 0.f;

#define STAGE_A_F32(A_, K_)                                                    \
    _Pragma("unroll")                                                          \
    for (int r = 0; r < 8; r++) {                                              \
        int row = r * 16 + (tid >> 3), c4 = tid & 7;                           \
        float4 v = *(const float4*)&(A_)[(size_t)(m0 + row) * (K_) + k0 + c4 * 4]; \
        u32t hh0, ll0, hh1, ll1;                                               \
        split2(v.x, v.y, hh0, ll0);                                            \
        split2(v.z, v.w, hh1, ll1);                                            \
        *(u32t*)&sAh[row * SPAD + c4 * 4]     = hh0;                           \
        *(u32t*)&sAh[row * SPAD + c4 * 4 + 2] = hh1;                           \
        *(u32t*)&sAl[row * SPAD + c4 * 4]     = ll0;                           \
        *(u32t*)&sAl[row * SPAD + c4 * 4 + 2] = ll1;                           \
    }

#define STAGE_B_ASYNC(buf_, Bh_, Bl_, K_, kk_)                                 \
    _Pragma("unroll")                                                          \
    for (int r = 0; r < 4; r++) {                                              \
        int n = r * 32 + (tid >> 2), q = tid & 3;                              \
        CP16(&sBh[((buf_) * 128 + n) * SPAD + q * 8],                          \
             &(Bh_)[(size_t)(bn + n) * (K_) + (kk_) + q * 8]);                 \
        CP16(&sBl[((buf_) * 128 + n) * SPAD + q * 8],                          \
             &(Bl_)[(size_t)(bn + n) * (K_) + (kk_) + q * 8]);                 \
    }                                                                          \
    CP_COMMIT();

#define TILE_COMPUTE(cur_)                                                     \
    _Pragma("unroll")                                                          \
    for (int ks = 0; ks < 32; ks += 16) {                                      \
        u32t ah[4][4], al[4][4], bfr[4][4];                                    \
        int arow = mw * 64 + (lane & 15);                                      \
        int acol = ks + ((lane >> 4) << 3);                                    \
        _Pragma("unroll")                                                      \
        for (int i = 0; i < 4; i++) {                                          \
            ldsm4(ah[i], (u32t)__cvta_generic_to_shared(&sAh[(arow + i * 16) * SPAD + acol])); \
            ldsm4(al[i], (u32t)__cvta_generic_to_shared(&sAl[(arow + i * 16) * SPAD + acol])); \
        }                                                                      \
        int gq = lane >> 3, lr = lane & 7;                                     \
        int brow_off = lr + ((gq >> 1) << 3);                                  \
        int bcol = ks + ((gq & 1) << 3);                                       \
        _Pragma("unroll")                                                      \
        for (int j = 0; j < 4; j++)                                            \
            ldsm4(bfr[j], (u32t)__cvta_generic_to_shared(                      \
                &sBh[((cur_) * 128 + nw * 64 + j * 16 + brow_off) * SPAD + bcol])); \
        _Pragma("unroll")                                                      \
        for (int i = 0; i < 4; i++)                                            \
            _Pragma("unroll")                                                  \
            for (int j = 0; j < 8; j++) {                                      \
                u32t b0 = bfr[j >> 1][(j & 1) * 2], b1 = bfr[j >> 1][(j & 1) * 2 + 1]; \
                mma16816(d[i][j], ah[i], b0, b1);                              \
                mma16816(d[i][j], al[i], b0, b1);                              \
            }                                                                  \
        _Pragma("unroll")                                                      \
        for (int j = 0; j < 4; j++)                                            \
            ldsm4(bfr[j], (u32t)__cvta_generic_to_shared(                      \
                &sBl[((cur_) * 128 + nw * 64 + j * 16 + brow_off) * SPAD + bcol])); \
        _Pragma("unroll")                                                      \
        for (int i = 0; i < 4; i++)                                            \
            _Pragma("unroll")                                                  \
            for (int j = 0; j < 8; j++)                                        \
                mma16816(d[i][j], ah[i],                                       \
                         bfr[j >> 1][(j & 1) * 2], bfr[j >> 1][(j & 1) * 2 + 1]); \
    }

#define MMA_PIPE(A_, Bh_, Bl_, K_)                                             \
    {                                                                          \
        STAGE_B_ASYNC(0, Bh_, Bl_, K_, 0)                                      \
        const int nt = (K_) >> 5;                                              \
        for (int kt = 0; kt < nt; kt++) {                                      \
            const int k0 = kt << 5;                                            \
            const int cur = kt & 1;                                            \
            STAGE_A_F32(A_, K_)                                                \
            if (kt + 1 < nt) {                                                 \
                STAGE_B_ASYNC(cur ^ 1, Bh_, Bl_, K_, k0 + 32)                  \
                asm volatile("cp.async.wait_group 1;" ::: "memory");           \
            } else {                                                           \
                asm volatile("cp.async.wait_group 0;" ::: "memory");           \
            }                                                                  \
            __syncthreads();                                                   \
            TILE_COMPUTE(cur)                                                  \
            __syncthreads();                                                   \
        }                                                                      \
    }

// ---------------- plain / relu GEMM ------------------------------------------
template <bool RELU>
__global__ __launch_bounds__(128) void k_mma(const float* __restrict__ A,
                                             const u16t* __restrict__ Bh,
                                             const u16t* __restrict__ Bl,
                                             const float* __restrict__ bias,
                                             float* __restrict__ C,
                                             int N, int K) {
    DECL_SMEM
    const int m0 = blockIdx.y * 128, bn = blockIdx.x * 128;
    DECL_MMA_VARS
    MMA_PIPE(A, Bh, Bl, K)
#pragma unroll
    for (int i = 0; i < 4; i++)
#pragma unroll
        for (int j = 0; j < 8; j++) {
            int row = m0 + mw * 64 + i * 16 + (lane >> 2);
            int col = bn + nw * 64 + j * 8 + (lane & 3) * 2;
            float b0 = bias[col], b1 = bias[col + 1];
            float c0 = d[i][j][0] + b0, c1 = d[i][j][1] + b1;
            float c2 = d[i][j][2] + b0, c3 = d[i][j][3] + b1;
            if (RELU) {
                c0 = fmaxf(c0, 0.f); c1 = fmaxf(c1, 0.f);
                c2 = fmaxf(c2, 0.f); c3 = fmaxf(c3, 0.f);
            }
            *(float2*)&C[(size_t)row * N + col] = make_float2(c0, c1);
            *(float2*)&C[(size_t)(row + 8) * N + col] = make_float2(c2, c3);
        }
}

// ---------------- gemm2 fused with LN + residual into g_x -------------------
__global__ __launch_bounds__(128) void k_mma_ln(const float* __restrict__ A,
                                                const u16t* __restrict__ Bh,
                                                const u16t* __restrict__ Bl,
                                                const float* __restrict__ bias,
                                                const float* __restrict__ lg,
                                                const float* __restrict__ lb,
                                                int K) {
    DECL_SMEM
    const int m0 = blockIdx.y * 128, bn = 0;
    DECL_MMA_VARS
    MMA_PIPE(A, Bh, Bl, K)

    // staging smem is dead now — alias LN stat buffers onto it
    float (*ps)[9]  = (float (*)[9])sAh;
    float (*pq)[9]  = (float (*)[9])sAl;
    float* smu      = (float*)sBh;
    float* srs      = ((float*)sBh) + 128;

    float bj0[8], bj1[8];
#pragma unroll
    for (int j = 0; j < 8; j++) {
        int col = nw * 64 + j * 8 + (lane & 3) * 2;
        bj0[j] = bias[col]; bj1[j] = bias[col + 1];
    }
    int pcol = nw * 4 + (lane & 3);
#pragma unroll
    for (int i = 0; i < 4; i++) {
        float s0 = 0.f, q0 = 0.f, s1 = 0.f, q1 = 0.f;
#pragma unroll
        for (int j = 0; j < 8; j++) {
            d[i][j][0] += bj0[j]; d[i][j][1] += bj1[j];
            d[i][j][2] += bj0[j]; d[i][j][3] += bj1[j];
            s0 += d[i][j][0] + d[i][j][1];
            q0 += d[i][j][0] * d[i][j][0] + d[i][j][1] * d[i][j][1];
            s1 += d[i][j][2] + d[i][j][3];
            q1 += d[i][j][2] * d[i][j][2] + d[i][j][3] * d[i][j][3];
        }
        int r0 = mw * 64 + i * 16 + (lane >> 2);
        ps[r0][pcol] = s0; pq[r0][pcol] = q0;
        ps[r0 + 8][pcol] = s1; pq[r0 + 8][pcol] = q1;
    }
    __syncthreads();
    {
        float s = 0.f, q = 0.f;
#pragma unroll
        for (int c = 0; c < 8; c++) { s += ps[tid][c]; q += pq[tid][c]; }
        float mu = s * (1.f / 128.f);
        float var = q * (1.f / 128.f) - mu * mu;
        smu[tid] = mu;
        srs[tid] = rsqrtf(var + 1e-5f);
    }
    __syncthreads();

    float lgv0[8], lgv1[8], lbv0[8], lbv1[8];
#pragma unroll
    for (int j = 0; j < 8; j++) {
        int col = nw * 64 + j * 8 + (lane & 3) * 2;
        lgv0[j] = lg[col]; lgv1[j] = lg[col + 1];
        lbv0[j] = lb[col]; lbv1[j] = lb[col + 1];
    }
#pragma unroll
    for (int i = 0; i < 4; i++) {
        int r0 = mw * 64 + i * 16 + (lane >> 2);
        float mu0 = smu[r0], rs0 = srs[r0];
        float mu1 = smu[r0 + 8], rs1 = srs[r0 + 8];
#pragma unroll
        for (int j = 0; j < 8; j++) {
            int col = nw * 64 + j * 8 + (lane & 3) * 2;
            float* xr0 = &g_x[(size_t)(m0 + r0) * 128 + col];
            float* xr1 = &g_x[(size_t)(m0 + r0 + 8) * 128 + col];
            float2 x0 = *(float2*)xr0;
            float2 x1 = *(float2*)xr1;
            x0.x += (d[i][j][0] - mu0) * rs0 * lgv0[j] + lbv0[j];
            x0.y += (d[i][j][1] - mu0) * rs0 * lgv1[j] + lbv1[j];
            x1.x += (d[i][j][2] - mu1) * rs1 * lgv0[j] + lbv0[j];
            x1.y += (d[i][j][3] - mu1) * rs1 * lgv1[j] + lbv1[j];
            *(float2*)xr0 = x0;
            *(float2*)xr1 = x1;
        }
    }
}

// ---------------- gate (warp/node) -----------------------------------------
__global__ __launch_bounds__(256) void k_gate_warp(const float* __restrict__ lng,
                                                   const float* __restrict__ lnb,
                                                   const float* __restrict__ w2,
                                                   const float* __restrict__ b2) {
    int tid = threadIdx.x;
    int warp = tid >> 5, lane = tid & 31;
    int n = blockIdx.x * 8 + warp;
    const float4* h4 = (const float4*)(g_h + n * 256);
    float4 h0 = h4[lane * 2], h1 = h4[lane * 2 + 1];
    float s = h0.x + h0.y + h0.z + h0.w + h1.x + h1.y + h1.z + h1.w;
    float q = h0.x * h0.x + h0.y * h0.y + h0.z * h0.z + h0.w * h0.w
            + h1.x * h1.x + h1.y * h1.y + h1.z * h1.z + h1.w * h1.w;
#pragma unroll
    for (int o = 16; o > 0; o >>= 1) {
        s += __shfl_xor_sync(~0u, s, o);
        q += __shfl_xor_sync(~0u, q, o);
    }
    float mu = s * (1.f / 256.f);
    float var = q * (1.f / 256.f) - mu * mu;
    float rs = rsqrtf(var + 1e-5f);
    float4 g0 = *(const float4*)&lng[lane * 8], g1 = *(const float4*)&lng[lane * 8 + 4];
    float4 c0 = *(const float4*)&lnb[lane * 8], c1 = *(const float4*)&lnb[lane * 8 + 4];
    float4 w0 = *(const float4*)&w2[lane * 8],  w1 = *(const float4*)&w2[lane * 8 + 4];
    float t = fmaxf((h0.x - mu) * rs * g0.x + c0.x, 0.f) * w0.x
            + fmaxf((h0.y - mu) * rs * g0.y + c0.y, 0.f) * w0.y
            + fmaxf((h0.z - mu) * rs * g0.z + c0.z, 0.f) * w0.z
            + fmaxf((h0.w - mu) * rs * g0.w + c0.w, 0.f) * w0.w
            + fmaxf((h1.x - mu) * rs * g1.x + c1.x, 0.f) * w1.x
            + fmaxf((h1.y - mu) * rs * g1.y + c1.y, 0.f) * w1.y
            + fmaxf((h1.z - mu) * rs * g1.z + c1.z, 0.f) * w1.z
            + fmaxf((h1.w - mu) * rs * g1.w + c1.w, 0.f) * w1.w;
#pragma unroll
    for (int o = 16; o > 0; o >>= 1) t += __shfl_xor_sync(~0u, t, o);
    if (lane == 0) g_gate[n] = t + b2[0];
}

// ---------------- pool + head ----------------------------------------------
__global__ void k_pool() {
    __shared__ float sg[64], w[64], red[64];
    int b = blockIdx.x, tid = threadIdx.x;
    if (tid < 64) sg[tid] = g_gate[b * 64 + tid];
    __syncthreads();
    if (tid < 64) red[tid] = sg[tid];
    __syncthreads();
    for (int s = 32; s > 0; s >>= 1) {
        if (tid < s) red[tid] = fmaxf(red[tid], red[tid + s]);
        __syncthreads();
    }
    float m = red[0];
    __syncthreads();
    if (tid < 64) { w[tid] = expf(sg[tid] - m); red[tid] = w[tid]; }
    __syncthreads();
    for (int s = 32; s > 0; s >>= 1) {
        if (tid < s) red[tid] += red[tid + s];
        __syncthreads();
    }
    float den = red[0];
    __syncthreads();
    if (tid < 64) w[tid] /= den;
    __syncthreads();
    float acc = 0.f;
#pragma unroll 4
    for (int j = 0; j < 64; j++) acc += w[j] * g_x[(b * 64 + j) * DD + tid];
    g_pool[b * DD + tid] = acc;
}

__device__ __forceinline__ float geluf(float x) {
    return 0.5f * x * (1.f + erff(x * 0.70710678118654752f));
}
__device__ __forceinline__ void lnStat128(float acc, float* red, float* mu, float* rs) {
    int tid = threadIdx.x;
    red[tid] = acc;
    __syncthreads();
    for (int s = 64; s > 0; s >>= 1) {
        if (tid < s) red[tid] += red[tid + s];
        __syncthreads();
    }
    float m = red[0] * (1.f / 128.f);
    __syncthreads();
    float dd = acc - m;
    red[tid] = dd * dd;
    __syncthreads();
    for (int s = 64; s > 0; s >>= 1) {
        if (tid < s) red[tid] += red[tid + s];
        __syncthreads();
    }
    float r = rsqrtf(red[0] * (1.f / 128.f) + 1e-5f);
    __syncthreads();
    *mu = m; *rs = r;
}
__global__ void k_head(const float* __restrict__ fc1W, const float* __restrict__ fc1b,
                       const float* __restrict__ ln1g, const float* __restrict__ ln1b,
                       const float* __restrict__ fc2W, const float* __restrict__ fc2b,
                       const float* __restrict__ ln2g, const float* __restrict__ ln2b,
                       const float* __restrict__ pW1, const float* __restrict__ pb1,
                       const float* __restrict__ pW2, const float* __restrict__ pb2,
                       float* __restrict__ out) {
    __shared__ float v[128], h1[128], red[128];
    int b = blockIdx.x, tid = threadIdx.x;
    v[tid] = g_pool[b * DD + tid];
    __syncthreads();
    for (int r = 0; r < 2; r++) {
        const float* W1 = fc1W + r * 16384;
        float acc = fc1b[r * 128 + tid];
        for (int k = 0; k < 128; k++) acc += v[k] * W1[k * 128 + tid];
        float mu, rs;
        lnStat128(acc, red, &mu, &rs);
        float ln = (acc - mu) * rs * ln1g[r * 128 + tid] + ln1b[r * 128 + tid];
        h1[tid] = geluf(ln);
        __syncthreads();
        const float* W2 = fc2W + r * 16384;
        float acc2 = fc2b[r * 128 + tid];
        for (int k = 0; k < 128; k++) acc2 += h1[k] * W2[k * 128 + tid];
        lnStat128(acc2, red, &mu, &rs);
        float ln2 = (acc2 - mu) * rs * ln2g[r * 128 + tid] + ln2b[r * 128 + tid];
        __syncthreads();
        v[tid] += ln2;
        __syncthreads();
    }
    float acc = pb1[tid];
    for (int k = 0; k < 128; k++) acc += v[k] * pW1[k * 128 + tid];
    h1[tid] = geluf(acc);
    __syncthreads();
    if (tid < 12) {
        float o = pb2[tid];
        for (int k = 0; k < 128; k++) o += h1[k] * pW2[k * 12 + tid];
        out[b * 12 + tid] = o;
    }
}

// ---- warm up full launch path in static init (pre-snapshot; zeros safe) ---
namespace {
struct WarmLaunch {
    WarmLaunch() {
        setenv("CUDA_MODULE_LOADING", "EAGER", 1);
        cudaSetDevice(0);
        cudaFree(0);
        void* pv = nullptr;
        cudaGetSymbolAddress(&pv, g_x);    p_x = (float*)pv;
        cudaGetSymbolAddress(&pv, g_agg);  p_agg = (float*)pv;
        cudaGetSymbolAddress(&pv, g_h);    p_h = (float*)pv;
        cudaGetSymbolAddress(&pv, g_pool); p_pool = (float*)pv;
        cudaGetSymbolAddress(&pv, g_wh);   p_wh = (u16t*)pv;
        cudaGetSymbolAddress(&pv, g_wl);   p_wl = (u16t*)pv;
        int* icsr = nullptr; int* icnt = nullptr;
        cudaGetSymbolAddress(&pv, g_csr);  icsr = (int*)pv;
        cudaGetSymbolAddress(&pv, g_cnt);  icnt = (int*)pv;

        cudaFuncSetAttribute(k_mma<true>,  cudaFuncAttributeMaxDynamicSharedMemorySize, DSMEM_BYTES);
        cudaFuncSetAttribute(k_mma<false>, cudaFuncAttributeMaxDynamicSharedMemorySize, DSMEM_BYTES);
        cudaFuncSetAttribute(k_mma_ln,     cudaFuncAttributeMaxDynamicSharedMemorySize, DSMEM_BYTES);

        k_zero_cnt<<<NODES / 256, 256>>>();
        k_scan<<<1, 1024>>>();
        k_init_x<<<NODES, DD>>>(p_h, icnt, p_x);
        k_count<<<E_NUM / 256, 256>>>(icsr);
        k_fill<<<E_NUM / 256, 256>>>(icsr);
        k_aggregate<<<NODES / 8, 256>>>(icsr, icnt, p_x);
        k_prep_w<<<896, 256>>>(p_x, p_x, p_x);
        k_mma<true><<<dim3(2, 256), 128, DSMEM_BYTES>>>(p_agg, p_wh, p_wl, p_pool, p_h, 256, 128);
        k_mma<false><<<dim3(2, 256), 128, DSMEM_BYTES>>>(p_x, p_wh, p_wl, p_pool, p_h, 256, 128);
        k_mma_ln<<<dim3(1, 256), 128, DSMEM_BYTES>>>(p_h, p_wh, p_wl, p_pool, p_x, p_x, 256);
        k_gate_warp<<<NODES / 8, 256>>>(p_x, p_x, p_x, p_x);
        k_pool<<<NGRAPH, 128>>>();
        k_head<<<NGRAPH, 128>>>(p_x, p_x, p_x, p_x, p_x, p_x, p_x, p_x,
                                p_x, p_x, p_x, p_x, p_pool);
        cudaDeviceSynchronize();
    }
};
WarmLaunch s_warmLaunch;
}

// ---------------- launch ----------------------------------------------------
extern "C" void kernel_launch(void* const* d_in, const int* in_sizes, int n_in,
                              void* d_out, int out_size) {
    const float* logits     = (const float*)d_in[0];
    const int*   atom_feat  = (const int*)d_in[2];
    const int*   edge_index = (const int*)d_in[3];
    const int*   edge_attr  = (const int*)d_in[4];
    const float* atom_emb   = (const float*)d_in[6];
    const float* edge_emb   = (const float*)d_in[7];
    const float* gnn_W1     = (const float*)d_in[8];
    const float* gnn_b1     = (const float*)d_in[9];
    const float* gnn_W2     = (const float*)d_in[10];
    const float* gnn_b2     = (const float*)d_in[11];
    const float* gnn_ln_g   = (const float*)d_in[12];
    const float* gnn_ln_b   = (const float*)d_in[13];
    const float* gate_W1    = (const float*)d_in[14];
    const float* gate_b1    = (const float*)d_in[15];
    const float* gate_ln_g  = (const float*)d_in[16];
    const float* gate_ln_b  = (const float*)d_in[17];
    const float* gate_W2    = (const float*)d_in[18];
    const float* gate_b2    = (const float*)d_in[19];
    const float* res_fc1_W  = (const float*)d_in[20];
    const float* res_fc1_b  = (const float*)d_in[21];
    const float* res_ln1_g  = (const float*)d_in[22];
    const float* res_ln1_b  = (const float*)d_in[23];
    const float* res_fc2_W  = (const float*)d_in[24];
    const float* res_fc2_b  = (const float*)d_in[25];
    const float* res_ln2_g  = (const float*)d_in[26];
    const float* res_ln2_b  = (const float*)d_in[27];
    const float* pred_W1    = (const float*)d_in[28];
    const float* pred_b1    = (const float*)d_in[29];
    const float* pred_W2    = (const float*)d_in[30];
    const float* pred_b2    = (const float*)d_in[31];
    float* out = (float*)d_out;

    const int* e_src = edge_index;
    const int* e_dst = edge_index + E_NUM;

    k_zero_cnt<<<NODES / 256, 256>>>();
    k_count<<<E_NUM / 256, 256>>>(e_dst);
    k_scan<<<1, 1024>>>();
    k_fill<<<E_NUM / 256, 256>>>(e_dst);

    k_init_x<<<NODES, DD>>>(logits, atom_feat, atom_emb);
    k_prep_w<<<896, 256>>>(gnn_W1, gnn_W2, gate_W1);

    for (int l = 0; l < NLAYER; l++) {
        k_aggregate<<<NODES / 8, 256>>>(e_src, edge_attr, edge_emb);
        // h = relu(agg @ W1 + b1)
        k_mma<true><<<dim3(2, 256), 128, DSMEM_BYTES>>>(
            p_agg, p_wh + W1_OFF(l), p_wl + W1_OFF(l),
            gnn_b1 + l * 256, p_h, 256, 128);
        // x += LN(h @ W2 + b2)   (fused)
        k_mma_ln<<<dim3(1, 256), 128, DSMEM_BYTES>>>(
            p_h, p_wh + W2_OFF(l), p_wl + W2_OFF(l),
            gnn_b2 + l * 128,
            gnn_ln_g + l * 128, gnn_ln_b + l * 128, 256);
    }

    // gate hidden = x @ gate_W1 + b1
    k_mma<false><<<dim3(2, 256), 128, DSMEM_BYTES>>>(
        p_x, p_wh + GW_OFF, p_wl + GW_OFF, gate_b1, p_h, 256, 128);
    k_gate_warp<<<NODES / 8, 256>>>(gate_ln_g, gate_ln_b, gate_W2, gate_b2);
    k_pool<<<NGRAPH, 128>>>();
    k_head<<<NGRAPH, 128>>>(res_fc1_W, res_fc1_b, res_ln1_g, res_ln1_b,
                            res_fc2_W, res_fc2_b, res_ln2_g, res_ln2_b,
                            pred_W1, pred_b1, pred_W2, pred_b2, out);
    (void)in_sizes; (void)n_in; (void)out_size;
}